// round 15
// baseline (speedup 1.0000x reference)
#include <cuda_runtime.h>
#include <cuda_bf16.h>
#include <cstdint>

// Problem constants
#define N_ROWS   131072
#define DDIM     64
#define KCB      1024
#define DECAY    0.99f
#define ONEMD    0.01f
#define EPS      1e-5f
#define BIAS     512.0f      // validated: biased scores positive, min >= 2^8
#define WINDOW   0.7f        // validated rescore window

#define NGROUPS  (N_ROWS / 32)   // 4096 warp work units
#define GRID_A   148
#define BLOCK_A  512

// Output layout
#define OFF_Q    0
#define OFF_LOSS (N_ROWS*DDIM)
#define OFF_NCB  (OFF_LOSS + 1)
#define OFF_ECS  (OFF_NCB + DDIM*KCB)
#define OFF_EIS  (OFF_ECS + KCB)

// Scratch
__device__ int            g_idx[N_ROWS];
__device__ float          g_counts[KCB];
__device__ float          g_isum[KCB * DDIM];     // [k][d]
__device__ float          g_l2cb[KCB];
__device__ float          g_cs_sum;
__device__ float          g_ncbT[KCB * DDIM];     // [k][d]
__device__ float          g_loss[1];
__device__ int            g_work;
__device__ __nv_bfloat16  g_cbbf[KCB * DDIM];     // fragment-major bf16 image (128KB)

// ---------------------------------------------------------------------------
__device__ __forceinline__ uint32_t packbf(float lo, float hi) {
    __nv_bfloat162 h = __floats2bfloat162_rn(lo, hi);
    return *reinterpret_cast<uint32_t*>(&h);
}

__device__ __forceinline__ void mma16(float c[4], const uint32_t a[4],
                                      uint32_t b0, uint32_t b1) {
    asm volatile(
        "mma.sync.aligned.m16n8k16.row.col.f32.bf16.bf16.f32 "
        "{%0,%1,%2,%3},{%4,%5,%6,%7},{%8,%9},{%0,%1,%2,%3};"
        : "+f"(c[0]), "+f"(c[1]), "+f"(c[2]), "+f"(c[3])
        : "r"(a[0]), "r"(a[1]), "r"(a[2]), "r"(a[3]), "r"(b0), "r"(b1));
}

__device__ __forceinline__ void cp_async16(uint32_t smem_dst, const void* gsrc) {
    asm volatile("cp.async.cg.shared.global [%0], [%1], 16;"
                 :: "r"(smem_dst), "l"(gsrc));
}

// sorted top-3 insert (ascending), 5 IMNMX — value-ordered container
__device__ __forceinline__ void top3(uint32_t p, uint32_t v[3]) {
    uint32_t a = max(v[0], p); v[0] = min(v[0], p);
    uint32_t b = max(v[1], a); v[1] = min(v[1], a);
    v[2] = min(v[2], b);
}

// Exact biased scores for a column PAIR (kb, kb+1). ONE body (I$-safe).
__device__ __forceinline__ void exact_pair(const float* __restrict__ X,
                                           const float* __restrict__ CB,
                                           const float* __restrict__ s_l2b,
                                           int row, int kb,
                                           float& bd, int& bk) {
    const float4* xr = reinterpret_cast<const float4*>(X + (size_t)row * DDIM);
    float a0 = 0.f, a1 = 0.f, a2 = 0.f, a3 = 0.f;
    float e0 = 0.f, e1 = 0.f, e2 = 0.f, e3 = 0.f;
    #pragma unroll
    for (int jj = 0; jj < 16; ++jj) {
        float4 xv = xr[jj];
        float2 cb0 = *reinterpret_cast<const float2*>(&CB[(4 * jj + 0) * KCB + kb]);
        float2 cb1 = *reinterpret_cast<const float2*>(&CB[(4 * jj + 1) * KCB + kb]);
        float2 cb2 = *reinterpret_cast<const float2*>(&CB[(4 * jj + 2) * KCB + kb]);
        float2 cb3 = *reinterpret_cast<const float2*>(&CB[(4 * jj + 3) * KCB + kb]);
        a0 = fmaf(xv.x, cb0.x, a0); e0 = fmaf(xv.x, cb0.y, e0);
        a1 = fmaf(xv.y, cb1.x, a1); e1 = fmaf(xv.y, cb1.y, e1);
        a2 = fmaf(xv.z, cb2.x, a2); e2 = fmaf(xv.z, cb2.y, e2);
        a3 = fmaf(xv.w, cb3.x, a3); e3 = fmaf(xv.w, cb3.y, e3);
    }
    float d0 = fmaf(-2.f, (a0 + a1) + (a2 + a3), s_l2b[kb]);
    float d1 = fmaf(-2.f, (e0 + e1) + (e2 + e3), s_l2b[kb + 1]);
    if (d0 < bd || (d0 == bd && kb < bk))     { bd = d0; bk = kb; }
    if (d1 < bd || (d1 == bd && kb + 1 < bk)) { bd = d1; bk = kb + 1; }
}

// ---------------------------------------------------------------------------
// Launch 0: zero g_isum + build fragment-major bf16 image, ks-PAIR interleaved.
// (layout identical to R14)
// ---------------------------------------------------------------------------
__global__ void k_init_image(const float* __restrict__ cb) {
    int e = blockIdx.x * blockDim.x + threadIdx.x;   // 0..32767

    reinterpret_cast<float2*>(g_isum)[e] = make_float2(0.f, 0.f);

    int reg   = e & 1;
    int khalf = (e >> 1) & 1;
    int lane  = (e >> 2) & 31;
    int kp    = (e >> 7) & 1;
    int nb    = (e >> 8) & 7;
    int tt    = (e >> 11) & 15;
    int ks = kp * 2 + khalf;
    int g = lane >> 2, t = lane & 3;
    int n  = tt * 64 + nb * 8 + g;
    int d0 = ks * 16 + reg * 8 + t * 2;
    float x0 = cb[d0 * KCB + n];
    float x1 = cb[(d0 + 1) * KCB + n];
    reinterpret_cast<uint32_t*>(g_cbbf)[e] = packbf(x0, x1);
}

// Launch 1: ||c_k||^2 + (block 0) sum of ema_cs
__global__ void k_l2cb(const float* __restrict__ cb,
                       const float* __restrict__ ema_cs) {
    __shared__ float part[256];
    int nl = threadIdx.x & 63, dq = threadIdx.x >> 6;
    int n = blockIdx.x * 64 + nl;
    float s = 0.0f;
    #pragma unroll
    for (int j = 0; j < 16; ++j) {
        float c = cb[(dq * 16 + j) * KCB + n];
        s = fmaf(c, c, s);
    }
    part[threadIdx.x] = s;
    __syncthreads();
    if (dq == 0)
        g_l2cb[n] = (part[nl] + part[64 + nl]) + (part[128 + nl] + part[192 + nl]);

    if (blockIdx.x == 0) {
        int i = threadIdx.x;
        float v = ema_cs[i] + ema_cs[i + 256] + ema_cs[i + 512] + ema_cs[i + 768];
        __syncthreads();
        part[i] = v;
        __syncthreads();
        for (int st = 128; st > 0; st >>= 1) {
            if (i < st) part[i] += part[i + st];
            __syncthreads();
        }
        if (i == 0) g_cs_sum = part[0];
    }
}

// Launch 2: small zeroing — keeps argmin at ncu's launch idx 3
__global__ void k_zero_small() {
    int i = threadIdx.x;
    g_counts[i] = 0.0f;
    if (i == 0) { g_loss[0] = 0.0f; g_work = 0; }
}

// ---------------------------------------------------------------------------
// Launch 3 (ncu-profiled): single-pass bf16 tensor argmin.
// Dual-nb super-iteration: 4 independent MMA accumulator chains + quad-min
// (4-column) sorted top-3 container. Exact dual-dot rescore, vec atomics.
// ---------------------------------------------------------------------------
extern __shared__ float s_dyn[];

__global__ __launch_bounds__(BLOCK_A, 1) void k_argmin_scatter(
        const float* __restrict__ X, const float* __restrict__ CB)
{
    float*    s_l2 = s_dyn;                                    // 1024 floats (biased)
    uint32_t* s_cb = reinterpret_cast<uint32_t*>(s_dyn + KCB); // 32768 u32

    const int tid  = threadIdx.x;
    const int lane = tid & 31;
    const int g    = lane >> 2;
    const int t    = lane & 3;

    for (int i = tid; i < KCB; i += BLOCK_A) s_l2[i] = g_l2cb[i] + BIAS;
    {
        const uint32_t sb = (uint32_t)__cvta_generic_to_shared(s_cb);
        const float4* src = reinterpret_cast<const float4*>(g_cbbf);
        #pragma unroll
        for (int j = 0; j < 16; ++j) {
            int e = tid + j * 512;
            cp_async16(sb + e * 16, src + e);
        }
        asm volatile("cp.async.commit_group;");
        asm volatile("cp.async.wait_group 0;");
    }
    __syncthreads();

    const float INF = __int_as_float(0x7f800000);

    for (;;) {
        int gid = 0;
        if (lane == 0) gid = atomicAdd(&g_work, 1);
        gid = __shfl_sync(0xffffffffu, gid, 0);
        if (gid >= NGROUPS) break;

        const int base = gid * 32;

        // A fragments (bf16), 2 m-tiles = 32 rows
        uint32_t Ah[2][4][4];
        #pragma unroll
        for (int m = 0; m < 2; ++m) {
            const float* xa = X + (size_t)(base + m * 16 + g) * DDIM;
            const float* xb = xa + 8 * DDIM;
            #pragma unroll
            for (int ks = 0; ks < 4; ++ks) {
                int ci = ks * 16 + 2 * t;
                Ah[m][ks][0] = packbf(xa[ci],     xa[ci + 1]);
                Ah[m][ks][1] = packbf(xb[ci],     xb[ci + 1]);
                Ah[m][ks][2] = packbf(xa[ci + 8], xa[ci + 9]);
                Ah[m][ks][3] = packbf(xb[ci + 8], xb[ci + 9]);
            }
        }

        // sorted top-3 of packed QUAD-minima per row-var
        uint32_t v[4][3];
        #pragma unroll
        for (int rv = 0; rv < 4; ++rv)
            v[rv][0] = v[rv][1] = v[rv][2] = 0xFFFFFFFFu;

        #pragma unroll 1
        for (int tt = 0; tt < 16; ++tt) {
            #pragma unroll
            for (int nbp = 0; nbp < 4; ++nbp) {
                const int nb0 = 2 * nbp, nb1 = 2 * nbp + 1;
                // B fragments for both nb blocks (LDS.128 each, conflict-free)
                uint4 ba0 = *reinterpret_cast<const uint4*>(
                    &s_cb[(tt * 16 + nb0 * 2 + 0) * 128 + lane * 4]);
                uint4 ba1 = *reinterpret_cast<const uint4*>(
                    &s_cb[(tt * 16 + nb0 * 2 + 1) * 128 + lane * 4]);
                uint4 bb0 = *reinterpret_cast<const uint4*>(
                    &s_cb[(tt * 16 + nb1 * 2 + 0) * 128 + lane * 4]);
                uint4 bb1 = *reinterpret_cast<const uint4*>(
                    &s_cb[(tt * 16 + nb1 * 2 + 1) * 128 + lane * 4]);

                // 4 independent accumulator chains (c0,c1 | d0,d1)
                float c0[4] = {0.f, 0.f, 0.f, 0.f};
                float c1[4] = {0.f, 0.f, 0.f, 0.f};
                float d0[4] = {0.f, 0.f, 0.f, 0.f};
                float d1[4] = {0.f, 0.f, 0.f, 0.f};
                mma16(c0, Ah[0][0], ba0.x, ba0.y);
                mma16(c1, Ah[1][0], ba0.x, ba0.y);
                mma16(d0, Ah[0][0], bb0.x, bb0.y);
                mma16(d1, Ah[1][0], bb0.x, bb0.y);
                mma16(c0, Ah[0][1], ba0.z, ba0.w);
                mma16(c1, Ah[1][1], ba0.z, ba0.w);
                mma16(d0, Ah[0][1], bb0.z, bb0.w);
                mma16(d1, Ah[1][1], bb0.z, bb0.w);
                mma16(c0, Ah[0][2], ba1.x, ba1.y);
                mma16(c1, Ah[1][2], ba1.x, ba1.y);
                mma16(d0, Ah[0][2], bb1.x, bb1.y);
                mma16(d1, Ah[1][2], bb1.x, bb1.y);
                mma16(c0, Ah[0][3], ba1.z, ba1.w);
                mma16(c1, Ah[1][3], ba1.z, ba1.w);
                mma16(d0, Ah[0][3], bb1.z, bb1.w);
                mma16(d1, Ah[1][3], bb1.z, bb1.w);

                const uint32_t colb = tt * 64 + nb0 * 8 + 2 * t;  // nb1 cols at +8
                float2 l2a = *reinterpret_cast<const float2*>(&s_l2[colb]);
                float2 l2b = *reinterpret_cast<const float2*>(&s_l2[colb + 8]);

                // quad-min over 4 columns (2 from each nb); pack low colb
                float q0 = fminf(
                    fminf(fmaf(-2.f, c0[0], l2a.x), fmaf(-2.f, c0[1], l2a.y)),
                    fminf(fmaf(-2.f, d0[0], l2b.x), fmaf(-2.f, d0[1], l2b.y)));
                float q1 = fminf(
                    fminf(fmaf(-2.f, c0[2], l2a.x), fmaf(-2.f, c0[3], l2a.y)),
                    fminf(fmaf(-2.f, d0[2], l2b.x), fmaf(-2.f, d0[3], l2b.y)));
                float q2 = fminf(
                    fminf(fmaf(-2.f, c1[0], l2a.x), fmaf(-2.f, c1[1], l2a.y)),
                    fminf(fmaf(-2.f, d1[0], l2b.x), fmaf(-2.f, d1[1], l2b.y)));
                float q3 = fminf(
                    fminf(fmaf(-2.f, c1[2], l2a.x), fmaf(-2.f, c1[3], l2a.y)),
                    fminf(fmaf(-2.f, d1[2], l2b.x), fmaf(-2.f, d1[3], l2b.y)));
                top3((__float_as_uint(q0) & 0xFFFFFC00u) | colb, v[0]);
                top3((__float_as_uint(q1) & 0xFFFFFC00u) | colb, v[1]);
                top3((__float_as_uint(q2) & 0xFFFFFC00u) | colb, v[2]);
                top3((__float_as_uint(q3) & 0xFFFFFC00u) | colb, v[3]);
            }
        }

        // quad-reduce min, window threshold, exact rescore (4 cols/candidate)
        int bi[4];
        #pragma unroll
        for (int rv = 0; rv < 4; ++rv) {
            uint32_t m = v[rv][0];
            m = min(m, __shfl_xor_sync(0xffffffffu, m, 1));
            m = min(m, __shfl_xor_sync(0xffffffffu, m, 2));
            const float thr = __uint_as_float(m & 0xFFFFFC00u) + WINDOW;

            const int row = base + rv * 8 + g;
            float bd = INF;
            int   bk = 0x7fffffff;
            #pragma unroll
            for (int sl = 0; sl < 3; ++sl) {
                uint32_t p = v[rv][sl];
                if (__uint_as_float(p & 0xFFFFFC00u) <= thr) {
                    int kb = (int)(p & 0x3FFu);
                    exact_pair(X, CB, s_l2, row, kb, bd, bk);
                    exact_pair(X, CB, s_l2, row, kb + 8, bd, bk);
                }
            }
            #pragma unroll
            for (int off = 1; off < 4; off <<= 1) {
                float od = __shfl_xor_sync(0xffffffffu, bd, off);
                int   ok = __shfl_xor_sync(0xffffffffu, bk, off);
                if (od < bd || (od == bd && ok < bk)) { bd = od; bk = ok; }
            }
            bi[rv] = bk;
        }

        if (t == 0) {
            #pragma unroll
            for (int rv = 0; rv < 4; ++rv) {
                g_idx[base + rv * 8 + g] = bi[rv];
                atomicAdd(&g_counts[bi[rv]], 1.0f);
            }
        }

        // scatter input sums: float4 vector atomics, 2 rows per iteration
        const float4* X4 = reinterpret_cast<const float4*>(X);
        #pragma unroll
        for (int rr = 0; rr < 32; rr += 2) {
            int r   = rr + (lane >> 4);
            int src = ((rr & 7) + (lane >> 4)) * 4;
            int idx = __shfl_sync(0xffffffffu, bi[rr >> 3], src);
            float4 vv = X4[(size_t)(base + r) * 16 + (lane & 15)];
            atomicAdd(reinterpret_cast<float4*>(g_isum + idx * DDIM) + (lane & 15), vv);
        }
    }
}

// ---------------------------------------------------------------------------
// Launch 4: fused EMA (cluster size + input sum + new codebook)
// ---------------------------------------------------------------------------
__global__ __launch_bounds__(256) void k_ema(
        const float* __restrict__ ema_cs,
        const float* __restrict__ ema_eis,
        float* __restrict__ out)
{
    int i = blockIdx.x * blockDim.x + threadIdx.x;   // 0..65535
    int k = i & (KCB - 1);
    int d = i >> 10;

    float ne = DECAY * ema_cs[k] + ONEMD * g_counts[k];
    if (d == 0) out[OFF_ECS + k] = ne;

    const float n = DECAY * g_cs_sum + ONEMD * (float)N_ROWS;
    const float norm = (ne + EPS) / (n + (float)KCB * EPS);
    const float invcs = 1.0f / (norm * n);

    float eis = DECAY * ema_eis[d * KCB + k] + ONEMD * g_isum[k * DDIM + d];
    out[OFF_EIS + d * KCB + k] = eis;
    float nc = eis * invcs;
    out[OFF_NCB + d * KCB + k] = nc;
    g_ncbT[k * DDIM + d] = nc;
}

// ---------------------------------------------------------------------------
// Launch 5: gather + straight-through + loss (float4, 2-way MLP)
// ---------------------------------------------------------------------------
__global__ __launch_bounds__(256) void k_gather_loss(
        const float* __restrict__ X, float* __restrict__ out)
{
    const int H = (N_ROWS * DDIM / 4) / 2;
    const int e0 = blockIdx.x * blockDim.x + threadIdx.x;
    const int e1 = e0 + H;
    const float4* X4 = reinterpret_cast<const float4*>(X);
    const float4* Q4 = reinterpret_cast<const float4*>(g_ncbT);
    float4* O4 = reinterpret_cast<float4*>(out + OFF_Q);

    int i0 = g_idx[e0 >> 4], i1 = g_idx[e1 >> 4];
    float4 x0 = X4[e0], x1 = X4[e1];
    float4 q0 = Q4[(i0 << 4) | (e0 & 15)];
    float4 q1 = Q4[(i1 << 4) | (e1 & 15)];

    float acc = 0.0f;
    float dx, dy, dz, dw;
    float4 o;
    dx = q0.x - x0.x; dy = q0.y - x0.y; dz = q0.z - x0.z; dw = q0.w - x0.w;
    o.x = x0.x + dx; o.y = x0.y + dy; o.z = x0.z + dz; o.w = x0.w + dw;
    O4[e0] = o;
    acc = fmaf(dx, dx, acc); acc = fmaf(dy, dy, acc);
    acc = fmaf(dz, dz, acc); acc = fmaf(dw, dw, acc);
    dx = q1.x - x1.x; dy = q1.y - x1.y; dz = q1.z - x1.z; dw = q1.w - x1.w;
    o.x = x1.x + dx; o.y = x1.y + dy; o.z = x1.z + dz; o.w = x1.w + dw;
    O4[e1] = o;
    acc = fmaf(dx, dx, acc); acc = fmaf(dy, dy, acc);
    acc = fmaf(dz, dz, acc); acc = fmaf(dw, dw, acc);

    #pragma unroll
    for (int o2 = 16; o2 > 0; o2 >>= 1)
        acc += __shfl_down_sync(0xffffffffu, acc, o2);
    __shared__ float warpsum[8];
    int lane = threadIdx.x & 31, wid = threadIdx.x >> 5;
    if (lane == 0) warpsum[wid] = acc;
    __syncthreads();
    if (wid == 0) {
        float vv = (lane < 8) ? warpsum[lane] : 0.0f;
        #pragma unroll
        for (int o2 = 4; o2 > 0; o2 >>= 1)
            vv += __shfl_down_sync(0xffffffffu, vv, o2);
        if (lane == 0) atomicAdd(g_loss, vv);
    }
}

__global__ void k_loss_finalize(float* __restrict__ out) {
    out[OFF_LOSS] = g_loss[0] * (1.0f / (float)(N_ROWS * DDIM));
}

// ---------------------------------------------------------------------------
extern "C" void kernel_launch(void* const* d_in, const int* in_sizes, int n_in,
                              void* d_out, int out_size) {
    const float* X       = (const float*)d_in[0];
    const float* CB      = (const float*)d_in[1];
    const float* EMA_CS  = (const float*)d_in[2];
    const float* EMA_EIS = (const float*)d_in[3];
    float* out = (float*)d_out;

    static const size_t dyn_smem = KCB * 4 + KCB * DDIM * 2;   // 4KB + 128KB
    cudaFuncSetAttribute(k_argmin_scatter,
                         cudaFuncAttributeMaxDynamicSharedMemorySize,
                         (int)dyn_smem);

    k_init_image<<<128, 256>>>(CB);                          // 0
    k_l2cb<<<16, 256>>>(CB, EMA_CS);                         // 1
    k_zero_small<<<1, 1024>>>();                             // 2
    k_argmin_scatter<<<GRID_A, BLOCK_A, dyn_smem>>>(X, CB);  // 3 (ncu)
    k_ema<<<256, 256>>>(EMA_CS, EMA_EIS, out);               // 4
    k_gather_loss<<<4096, 256>>>(X, out);                    // 5
    k_loss_finalize<<<1, 1>>>(out);                          // 6
}

// round 16
// speedup vs baseline: 1.1714x; 1.1714x over previous
#include <cuda_runtime.h>
#include <cuda_bf16.h>
#include <cstdint>

// Problem constants
#define N_ROWS   131072
#define DDIM     64
#define KCB      1024
#define DECAY    0.99f
#define ONEMD    0.01f
#define EPS      1e-5f
#define BIAS     512.0f      // validated: biased scores positive, min >= 2^8
#define WINDOW   0.7f        // validated rescore window

#define NGROUPS  (N_ROWS / 32)   // 4096 warp work units
#define GRID_A   148
#define BLOCK_A  512
#define GRID_G   4096            // gather grid (arrival counter counts these)

// Output layout
#define OFF_Q    0
#define OFF_LOSS (N_ROWS*DDIM)
#define OFF_NCB  (OFF_LOSS + 1)
#define OFF_ECS  (OFF_NCB + DDIM*KCB)
#define OFF_EIS  (OFF_ECS + KCB)

// Scratch
__device__ int            g_idx[N_ROWS];
__device__ float          g_counts[KCB];
__device__ float          g_isum[KCB * DDIM];     // [k][d]
__device__ float          g_l2cb[KCB];
__device__ float          g_cs_sum;
__device__ float          g_ncbT[KCB * DDIM];     // [k][d]
__device__ float          g_loss[1];
__device__ int            g_work;
__device__ int            g_done;
__device__ __nv_bfloat16  g_cbbf[KCB * DDIM];     // fragment-major bf16 image (128KB)

// ---------------------------------------------------------------------------
__device__ __forceinline__ uint32_t packbf(float lo, float hi) {
    __nv_bfloat162 h = __floats2bfloat162_rn(lo, hi);
    return *reinterpret_cast<uint32_t*>(&h);
}

__device__ __forceinline__ void mma16(float c[4], const uint32_t a[4],
                                      uint32_t b0, uint32_t b1) {
    asm volatile(
        "mma.sync.aligned.m16n8k16.row.col.f32.bf16.bf16.f32 "
        "{%0,%1,%2,%3},{%4,%5,%6,%7},{%8,%9},{%0,%1,%2,%3};"
        : "+f"(c[0]), "+f"(c[1]), "+f"(c[2]), "+f"(c[3])
        : "r"(a[0]), "r"(a[1]), "r"(a[2]), "r"(a[3]), "r"(b0), "r"(b1));
}

__device__ __forceinline__ void cp_async16(uint32_t smem_dst, const void* gsrc) {
    asm volatile("cp.async.cg.shared.global [%0], [%1], 16;"
                 :: "r"(smem_dst), "l"(gsrc));
}

// sorted top-3 insert (ascending), 5 IMNMX — value-ordered container
__device__ __forceinline__ void top3(uint32_t p, uint32_t v[3]) {
    uint32_t a = max(v[0], p); v[0] = min(v[0], p);
    uint32_t b = max(v[1], a); v[1] = min(v[1], a);
    v[2] = min(v[2], b);
}

// Exact biased scores for a column PAIR (kb, kb+1). ONE body (I$-safe).
__device__ __forceinline__ void exact_pair(const float* __restrict__ X,
                                           const float* __restrict__ CB,
                                           const float* __restrict__ s_l2b,
                                           int row, int kb,
                                           float& bd, int& bk) {
    const float4* xr = reinterpret_cast<const float4*>(X + (size_t)row * DDIM);
    float a0 = 0.f, a1 = 0.f, a2 = 0.f, a3 = 0.f;
    float e0 = 0.f, e1 = 0.f, e2 = 0.f, e3 = 0.f;
    #pragma unroll
    for (int jj = 0; jj < 16; ++jj) {
        float4 xv = xr[jj];
        float2 cb0 = *reinterpret_cast<const float2*>(&CB[(4 * jj + 0) * KCB + kb]);
        float2 cb1 = *reinterpret_cast<const float2*>(&CB[(4 * jj + 1) * KCB + kb]);
        float2 cb2 = *reinterpret_cast<const float2*>(&CB[(4 * jj + 2) * KCB + kb]);
        float2 cb3 = *reinterpret_cast<const float2*>(&CB[(4 * jj + 3) * KCB + kb]);
        a0 = fmaf(xv.x, cb0.x, a0); e0 = fmaf(xv.x, cb0.y, e0);
        a1 = fmaf(xv.y, cb1.x, a1); e1 = fmaf(xv.y, cb1.y, e1);
        a2 = fmaf(xv.z, cb2.x, a2); e2 = fmaf(xv.z, cb2.y, e2);
        a3 = fmaf(xv.w, cb3.x, a3); e3 = fmaf(xv.w, cb3.y, e3);
    }
    float d0 = fmaf(-2.f, (a0 + a1) + (a2 + a3), s_l2b[kb]);
    float d1 = fmaf(-2.f, (e0 + e1) + (e2 + e3), s_l2b[kb + 1]);
    if (d0 < bd || (d0 == bd && kb < bk))     { bd = d0; bk = kb; }
    if (d1 < bd || (d1 == bd && kb + 1 < bk)) { bd = d1; bk = kb + 1; }
}

// ---------------------------------------------------------------------------
// Launch 0: zero g_isum + build fragment-major bf16 image, ks-PAIR interleaved.
// ---------------------------------------------------------------------------
__global__ void k_init_image(const float* __restrict__ cb) {
    int e = blockIdx.x * blockDim.x + threadIdx.x;   // 0..32767

    reinterpret_cast<float2*>(g_isum)[e] = make_float2(0.f, 0.f);

    int reg   = e & 1;
    int khalf = (e >> 1) & 1;
    int lane  = (e >> 2) & 31;
    int kp    = (e >> 7) & 1;
    int nb    = (e >> 8) & 7;
    int tt    = (e >> 11) & 15;
    int ks = kp * 2 + khalf;
    int g = lane >> 2, t = lane & 3;
    int n  = tt * 64 + nb * 8 + g;
    int d0 = ks * 16 + reg * 8 + t * 2;
    float x0 = cb[d0 * KCB + n];
    float x1 = cb[(d0 + 1) * KCB + n];
    reinterpret_cast<uint32_t*>(g_cbbf)[e] = packbf(x0, x1);
}

// Launch 1: ||c_k||^2 + (block 0) sum of ema_cs
__global__ void k_l2cb(const float* __restrict__ cb,
                       const float* __restrict__ ema_cs) {
    __shared__ float part[256];
    int nl = threadIdx.x & 63, dq = threadIdx.x >> 6;
    int n = blockIdx.x * 64 + nl;
    float s = 0.0f;
    #pragma unroll
    for (int j = 0; j < 16; ++j) {
        float c = cb[(dq * 16 + j) * KCB + n];
        s = fmaf(c, c, s);
    }
    part[threadIdx.x] = s;
    __syncthreads();
    if (dq == 0)
        g_l2cb[n] = (part[nl] + part[64 + nl]) + (part[128 + nl] + part[192 + nl]);

    if (blockIdx.x == 0) {
        int i = threadIdx.x;
        float v = ema_cs[i] + ema_cs[i + 256] + ema_cs[i + 512] + ema_cs[i + 768];
        __syncthreads();
        part[i] = v;
        __syncthreads();
        for (int st = 128; st > 0; st >>= 1) {
            if (i < st) part[i] += part[i + st];
            __syncthreads();
        }
        if (i == 0) g_cs_sum = part[0];
    }
}

// Launch 2: small zeroing — keeps argmin at ncu's launch idx 3
__global__ void k_zero_small() {
    int i = threadIdx.x;
    g_counts[i] = 0.0f;
    if (i == 0) { g_loss[0] = 0.0f; g_work = 0; g_done = 0; }
}

// ---------------------------------------------------------------------------
// Launch 3 (ncu-profiled): single-pass bf16 tensor argmin, sorted top-3 of
// PAIR-minima, LDS.128 ks-pair B loads, interleaved c0/c1 MMA issue,
// exact dual-dot rescore, vector-atomic scatter.
// ---------------------------------------------------------------------------
extern __shared__ float s_dyn[];

__global__ __launch_bounds__(BLOCK_A, 1) void k_argmin_scatter(
        const float* __restrict__ X, const float* __restrict__ CB)
{
    float*    s_l2 = s_dyn;                                    // 1024 floats (biased)
    uint32_t* s_cb = reinterpret_cast<uint32_t*>(s_dyn + KCB); // 32768 u32

    const int tid  = threadIdx.x;
    const int lane = tid & 31;
    const int g    = lane >> 2;
    const int t    = lane & 3;

    for (int i = tid; i < KCB; i += BLOCK_A) s_l2[i] = g_l2cb[i] + BIAS;
    {
        const uint32_t sb = (uint32_t)__cvta_generic_to_shared(s_cb);
        const float4* src = reinterpret_cast<const float4*>(g_cbbf);
        #pragma unroll
        for (int j = 0; j < 16; ++j) {
            int e = tid + j * 512;
            cp_async16(sb + e * 16, src + e);
        }
        asm volatile("cp.async.commit_group;");
        asm volatile("cp.async.wait_group 0;");
    }
    __syncthreads();

    const float INF = __int_as_float(0x7f800000);

    for (;;) {
        int gid = 0;
        if (lane == 0) gid = atomicAdd(&g_work, 1);
        gid = __shfl_sync(0xffffffffu, gid, 0);
        if (gid >= NGROUPS) break;

        const int base = gid * 32;

        // A fragments (bf16), 2 m-tiles = 32 rows
        uint32_t Ah[2][4][4];
        #pragma unroll
        for (int m = 0; m < 2; ++m) {
            const float* xa = X + (size_t)(base + m * 16 + g) * DDIM;
            const float* xb = xa + 8 * DDIM;
            #pragma unroll
            for (int ks = 0; ks < 4; ++ks) {
                int ci = ks * 16 + 2 * t;
                Ah[m][ks][0] = packbf(xa[ci],     xa[ci + 1]);
                Ah[m][ks][1] = packbf(xb[ci],     xb[ci + 1]);
                Ah[m][ks][2] = packbf(xa[ci + 8], xa[ci + 9]);
                Ah[m][ks][3] = packbf(xb[ci + 8], xb[ci + 9]);
            }
        }

        // sorted top-3 of packed pair-minima per row-var
        uint32_t v[4][3];
        #pragma unroll
        for (int rv = 0; rv < 4; ++rv)
            v[rv][0] = v[rv][1] = v[rv][2] = 0xFFFFFFFFu;

        #pragma unroll 2
        for (int tt = 0; tt < 16; ++tt) {
            #pragma unroll
            for (int nb = 0; nb < 8; ++nb) {
                float c0[4] = {0.f, 0.f, 0.f, 0.f};
                float c1[4] = {0.f, 0.f, 0.f, 0.f};
                #pragma unroll
                for (int kp = 0; kp < 2; ++kp) {
                    uint4 b = *reinterpret_cast<const uint4*>(
                        &s_cb[(tt * 16 + nb * 2 + kp) * 128 + lane * 4]);
                    // interleave the two independent accumulator chains
                    mma16(c0, Ah[0][2 * kp],     b.x, b.y);
                    mma16(c1, Ah[1][2 * kp],     b.x, b.y);
                    mma16(c0, Ah[0][2 * kp + 1], b.z, b.w);
                    mma16(c1, Ah[1][2 * kp + 1], b.z, b.w);
                }
                const uint32_t colb = tt * 64 + nb * 8 + 2 * t;
                float2 l2p = *reinterpret_cast<const float2*>(&s_l2[colb]);

                float q0 = fminf(fmaf(-2.f, c0[0], l2p.x), fmaf(-2.f, c0[1], l2p.y));
                float q1 = fminf(fmaf(-2.f, c0[2], l2p.x), fmaf(-2.f, c0[3], l2p.y));
                float q2 = fminf(fmaf(-2.f, c1[0], l2p.x), fmaf(-2.f, c1[1], l2p.y));
                float q3 = fminf(fmaf(-2.f, c1[2], l2p.x), fmaf(-2.f, c1[3], l2p.y));
                top3((__float_as_uint(q0) & 0xFFFFFC00u) | colb, v[0]);
                top3((__float_as_uint(q1) & 0xFFFFFC00u) | colb, v[1]);
                top3((__float_as_uint(q2) & 0xFFFFFC00u) | colb, v[2]);
                top3((__float_as_uint(q3) & 0xFFFFFC00u) | colb, v[3]);
            }
        }

        // quad-reduce min, window threshold, exact rescore of candidate pairs
        int bi[4];
        #pragma unroll
        for (int rv = 0; rv < 4; ++rv) {
            uint32_t m = v[rv][0];
            m = min(m, __shfl_xor_sync(0xffffffffu, m, 1));
            m = min(m, __shfl_xor_sync(0xffffffffu, m, 2));
            const float thr = __uint_as_float(m & 0xFFFFFC00u) + WINDOW;

            const int row = base + rv * 8 + g;
            float bd = INF;
            int   bk = 0x7fffffff;
            #pragma unroll
            for (int sl = 0; sl < 3; ++sl) {
                uint32_t p = v[rv][sl];
                if (__uint_as_float(p & 0xFFFFFC00u) <= thr) {
                    int kb = (int)(p & 0x3FFu);
                    exact_pair(X, CB, s_l2, row, kb, bd, bk);
                }
            }
            #pragma unroll
            for (int off = 1; off < 4; off <<= 1) {
                float od = __shfl_xor_sync(0xffffffffu, bd, off);
                int   ok = __shfl_xor_sync(0xffffffffu, bk, off);
                if (od < bd || (od == bd && ok < bk)) { bd = od; bk = ok; }
            }
            bi[rv] = bk;
        }

        if (t == 0) {
            #pragma unroll
            for (int rv = 0; rv < 4; ++rv) {
                g_idx[base + rv * 8 + g] = bi[rv];
                atomicAdd(&g_counts[bi[rv]], 1.0f);
            }
        }

        // scatter input sums: float4 vector atomics, 2 rows per iteration
        const float4* X4 = reinterpret_cast<const float4*>(X);
        #pragma unroll
        for (int rr = 0; rr < 32; rr += 2) {
            int r   = rr + (lane >> 4);
            int src = ((rr & 7) + (lane >> 4)) * 4;
            int idx = __shfl_sync(0xffffffffu, bi[rr >> 3], src);
            float4 vv = X4[(size_t)(base + r) * 16 + (lane & 15)];
            atomicAdd(reinterpret_cast<float4*>(g_isum + idx * DDIM) + (lane & 15), vv);
        }
    }
}

// ---------------------------------------------------------------------------
// Launch 4: fused EMA (cluster size + input sum + new codebook)
// ---------------------------------------------------------------------------
__global__ __launch_bounds__(256) void k_ema(
        const float* __restrict__ ema_cs,
        const float* __restrict__ ema_eis,
        float* __restrict__ out)
{
    int i = blockIdx.x * blockDim.x + threadIdx.x;   // 0..65535
    int k = i & (KCB - 1);
    int d = i >> 10;

    float ne = DECAY * ema_cs[k] + ONEMD * g_counts[k];
    if (d == 0) out[OFF_ECS + k] = ne;

    const float n = DECAY * g_cs_sum + ONEMD * (float)N_ROWS;
    const float norm = (ne + EPS) / (n + (float)KCB * EPS);
    const float invcs = 1.0f / (norm * n);

    float eis = DECAY * ema_eis[d * KCB + k] + ONEMD * g_isum[k * DDIM + d];
    out[OFF_EIS + d * KCB + k] = eis;
    float nc = eis * invcs;
    out[OFF_NCB + d * KCB + k] = nc;
    g_ncbT[k * DDIM + d] = nc;
}

// ---------------------------------------------------------------------------
// Launch 5: gather + straight-through + loss + fused finalize (last block)
// ---------------------------------------------------------------------------
__global__ __launch_bounds__(256) void k_gather_loss(
        const float* __restrict__ X, float* __restrict__ out)
{
    const int H = (N_ROWS * DDIM / 4) / 2;
    const int e0 = blockIdx.x * blockDim.x + threadIdx.x;
    const int e1 = e0 + H;
    const float4* X4 = reinterpret_cast<const float4*>(X);
    const float4* Q4 = reinterpret_cast<const float4*>(g_ncbT);
    float4* O4 = reinterpret_cast<float4*>(out + OFF_Q);

    int i0 = g_idx[e0 >> 4], i1 = g_idx[e1 >> 4];
    float4 x0 = X4[e0], x1 = X4[e1];
    float4 q0 = Q4[(i0 << 4) | (e0 & 15)];
    float4 q1 = Q4[(i1 << 4) | (e1 & 15)];

    float acc = 0.0f;
    float dx, dy, dz, dw;
    float4 o;
    dx = q0.x - x0.x; dy = q0.y - x0.y; dz = q0.z - x0.z; dw = q0.w - x0.w;
    o.x = x0.x + dx; o.y = x0.y + dy; o.z = x0.z + dz; o.w = x0.w + dw;
    O4[e0] = o;
    acc = fmaf(dx, dx, acc); acc = fmaf(dy, dy, acc);
    acc = fmaf(dz, dz, acc); acc = fmaf(dw, dw, acc);
    dx = q1.x - x1.x; dy = q1.y - x1.y; dz = q1.z - x1.z; dw = q1.w - x1.w;
    o.x = x1.x + dx; o.y = x1.y + dy; o.z = x1.z + dz; o.w = x1.w + dw;
    O4[e1] = o;
    acc = fmaf(dx, dx, acc); acc = fmaf(dy, dy, acc);
    acc = fmaf(dz, dz, acc); acc = fmaf(dw, dw, acc);

    #pragma unroll
    for (int o2 = 16; o2 > 0; o2 >>= 1)
        acc += __shfl_down_sync(0xffffffffu, acc, o2);
    __shared__ float warpsum[8];
    __shared__ int   lastflag;
    int lane = threadIdx.x & 31, wid = threadIdx.x >> 5;
    if (lane == 0) warpsum[wid] = acc;
    __syncthreads();
    if (wid == 0) {
        float vv = (lane < 8) ? warpsum[lane] : 0.0f;
        #pragma unroll
        for (int o2 = 4; o2 > 0; o2 >>= 1)
            vv += __shfl_down_sync(0xffffffffu, vv, o2);
        if (lane == 0) {
            atomicAdd(g_loss, vv);
            __threadfence();
            int done = atomicAdd(&g_done, 1);
            lastflag = (done == GRID_G - 1);
        }
    }
    __syncthreads();
    if (lastflag && threadIdx.x == 0) {
        __threadfence();
        out[OFF_LOSS] = g_loss[0] * (1.0f / (float)(N_ROWS * DDIM));
    }
}

// ---------------------------------------------------------------------------
extern "C" void kernel_launch(void* const* d_in, const int* in_sizes, int n_in,
                              void* d_out, int out_size) {
    const float* X       = (const float*)d_in[0];
    const float* CB      = (const float*)d_in[1];
    const float* EMA_CS  = (const float*)d_in[2];
    const float* EMA_EIS = (const float*)d_in[3];
    float* out = (float*)d_out;

    static const size_t dyn_smem = KCB * 4 + KCB * DDIM * 2;   // 4KB + 128KB
    cudaFuncSetAttribute(k_argmin_scatter,
                         cudaFuncAttributeMaxDynamicSharedMemorySize,
                         (int)dyn_smem);

    k_init_image<<<128, 256>>>(CB);                          // 0
    k_l2cb<<<16, 256>>>(CB, EMA_CS);                         // 1
    k_zero_small<<<1, 1024>>>();                             // 2
    k_argmin_scatter<<<GRID_A, BLOCK_A, dyn_smem>>>(X, CB);  // 3 (ncu)
    k_ema<<<256, 256>>>(EMA_CS, EMA_EIS, out);               // 4
    k_gather_loss<<<GRID_G, 256>>>(X, out);                  // 5
}

// round 17
// speedup vs baseline: 1.1977x; 1.0225x over previous
#include <cuda_runtime.h>
#include <cuda_bf16.h>
#include <cstdint>

// Problem constants
#define N_ROWS   131072
#define DDIM     64
#define KCB      1024
#define DECAY    0.99f
#define ONEMD    0.01f
#define EPS      1e-5f
#define BIAS     512.0f      // validated: biased scores positive, min >= 2^8
#define WINDOW   0.7f        // validated rescore window

#define NGROUPS  (N_ROWS / 32)   // 4096 warp work units
#define GRID_A   148
#define BLOCK_A  512

// Output layout
#define OFF_Q    0
#define OFF_LOSS (N_ROWS*DDIM)
#define OFF_NCB  (OFF_LOSS + 1)
#define OFF_ECS  (OFF_NCB + DDIM*KCB)
#define OFF_EIS  (OFF_ECS + KCB)

// Scratch
__device__ int            g_idx[N_ROWS];
__device__ float          g_counts[KCB];
__device__ float          g_isum[KCB * DDIM];     // [k][d]
__device__ float          g_l2cb[KCB];
__device__ float          g_cs_sum;
__device__ float          g_ncbT[KCB * DDIM];     // [k][d]
__device__ float          g_loss[1];
__device__ int            g_work;
__device__ __nv_bfloat16  g_cbbf[KCB * DDIM];     // fragment-major bf16 image (128KB)

// ---------------------------------------------------------------------------
__device__ __forceinline__ uint32_t packbf(float lo, float hi) {
    __nv_bfloat162 h = __floats2bfloat162_rn(lo, hi);
    return *reinterpret_cast<uint32_t*>(&h);
}

__device__ __forceinline__ void mma16(float c[4], const uint32_t a[4],
                                      uint32_t b0, uint32_t b1) {
    asm volatile(
        "mma.sync.aligned.m16n8k16.row.col.f32.bf16.bf16.f32 "
        "{%0,%1,%2,%3},{%4,%5,%6,%7},{%8,%9},{%0,%1,%2,%3};"
        : "+f"(c[0]), "+f"(c[1]), "+f"(c[2]), "+f"(c[3])
        : "r"(a[0]), "r"(a[1]), "r"(a[2]), "r"(a[3]), "r"(b0), "r"(b1));
}

__device__ __forceinline__ void cp_async16(uint32_t smem_dst, const void* gsrc) {
    asm volatile("cp.async.cg.shared.global [%0], [%1], 16;"
                 :: "r"(smem_dst), "l"(gsrc));
}

// sorted top-3 insert (ascending), 5 IMNMX — value-ordered container
__device__ __forceinline__ void top3(uint32_t p, uint32_t v[3]) {
    uint32_t a = max(v[0], p); v[0] = min(v[0], p);
    uint32_t b = max(v[1], a); v[1] = min(v[1], a);
    v[2] = min(v[2], b);
}

// Exact biased scores for a column PAIR (kb, kb+1). ONE body (I$-safe).
__device__ __forceinline__ void exact_pair(const float* __restrict__ X,
                                           const float* __restrict__ CB,
                                           const float* __restrict__ s_l2b,
                                           int row, int kb,
                                           float& bd, int& bk) {
    const float4* xr = reinterpret_cast<const float4*>(X + (size_t)row * DDIM);
    float a0 = 0.f, a1 = 0.f, a2 = 0.f, a3 = 0.f;
    float e0 = 0.f, e1 = 0.f, e2 = 0.f, e3 = 0.f;
    #pragma unroll
    for (int jj = 0; jj < 16; ++jj) {
        float4 xv = xr[jj];
        float2 cb0 = *reinterpret_cast<const float2*>(&CB[(4 * jj + 0) * KCB + kb]);
        float2 cb1 = *reinterpret_cast<const float2*>(&CB[(4 * jj + 1) * KCB + kb]);
        float2 cb2 = *reinterpret_cast<const float2*>(&CB[(4 * jj + 2) * KCB + kb]);
        float2 cb3 = *reinterpret_cast<const float2*>(&CB[(4 * jj + 3) * KCB + kb]);
        a0 = fmaf(xv.x, cb0.x, a0); e0 = fmaf(xv.x, cb0.y, e0);
        a1 = fmaf(xv.y, cb1.x, a1); e1 = fmaf(xv.y, cb1.y, e1);
        a2 = fmaf(xv.z, cb2.x, a2); e2 = fmaf(xv.z, cb2.y, e2);
        a3 = fmaf(xv.w, cb3.x, a3); e3 = fmaf(xv.w, cb3.y, e3);
    }
    float d0 = fmaf(-2.f, (a0 + a1) + (a2 + a3), s_l2b[kb]);
    float d1 = fmaf(-2.f, (e0 + e1) + (e2 + e3), s_l2b[kb + 1]);
    if (d0 < bd || (d0 == bd && kb < bk))     { bd = d0; bk = kb; }
    if (d1 < bd || (d1 == bd && kb + 1 < bk)) { bd = d1; bk = kb + 1; }
}

// ---------------------------------------------------------------------------
// Launch 0: zero g_isum + build fragment-major bf16 image, ks-PAIR interleaved.
// ---------------------------------------------------------------------------
__global__ void k_init_image(const float* __restrict__ cb) {
    int e = blockIdx.x * blockDim.x + threadIdx.x;   // 0..32767

    reinterpret_cast<float2*>(g_isum)[e] = make_float2(0.f, 0.f);

    int reg   = e & 1;
    int khalf = (e >> 1) & 1;
    int lane  = (e >> 2) & 31;
    int kp    = (e >> 7) & 1;
    int nb    = (e >> 8) & 7;
    int tt    = (e >> 11) & 15;
    int ks = kp * 2 + khalf;
    int g = lane >> 2, t = lane & 3;
    int n  = tt * 64 + nb * 8 + g;
    int d0 = ks * 16 + reg * 8 + t * 2;
    float x0 = cb[d0 * KCB + n];
    float x1 = cb[(d0 + 1) * KCB + n];
    reinterpret_cast<uint32_t*>(g_cbbf)[e] = packbf(x0, x1);
}

// Launch 1: ||c_k||^2 + (block 0) sum of ema_cs
__global__ void k_l2cb(const float* __restrict__ cb,
                       const float* __restrict__ ema_cs) {
    __shared__ float part[256];
    int nl = threadIdx.x & 63, dq = threadIdx.x >> 6;
    int n = blockIdx.x * 64 + nl;
    float s = 0.0f;
    #pragma unroll
    for (int j = 0; j < 16; ++j) {
        float c = cb[(dq * 16 + j) * KCB + n];
        s = fmaf(c, c, s);
    }
    part[threadIdx.x] = s;
    __syncthreads();
    if (dq == 0)
        g_l2cb[n] = (part[nl] + part[64 + nl]) + (part[128 + nl] + part[192 + nl]);

    if (blockIdx.x == 0) {
        int i = threadIdx.x;
        float v = ema_cs[i] + ema_cs[i + 256] + ema_cs[i + 512] + ema_cs[i + 768];
        __syncthreads();
        part[i] = v;
        __syncthreads();
        for (int st = 128; st > 0; st >>= 1) {
            if (i < st) part[i] += part[i + st];
            __syncthreads();
        }
        if (i == 0) g_cs_sum = part[0];
    }
}

// Launch 2: small zeroing — keeps argmin at ncu's launch idx 3
__global__ void k_zero_small() {
    int i = threadIdx.x;
    g_counts[i] = 0.0f;
    if (i == 0) { g_loss[0] = 0.0f; g_work = 0; }
}

// ---------------------------------------------------------------------------
// Launch 3 (ncu-profiled): single-pass bf16 tensor argmin, sorted top-3 of
// PAIR-minima, LDS.128 ks-pair B loads, exact dual-dot rescore, vec atomics.
// R14-exact.
// ---------------------------------------------------------------------------
extern __shared__ float s_dyn[];

__global__ __launch_bounds__(BLOCK_A, 1) void k_argmin_scatter(
        const float* __restrict__ X, const float* __restrict__ CB)
{
    float*    s_l2 = s_dyn;                                    // 1024 floats (biased)
    uint32_t* s_cb = reinterpret_cast<uint32_t*>(s_dyn + KCB); // 32768 u32

    const int tid  = threadIdx.x;
    const int lane = tid & 31;
    const int g    = lane >> 2;
    const int t    = lane & 3;

    for (int i = tid; i < KCB; i += BLOCK_A) s_l2[i] = g_l2cb[i] + BIAS;
    {
        const uint32_t sb = (uint32_t)__cvta_generic_to_shared(s_cb);
        const float4* src = reinterpret_cast<const float4*>(g_cbbf);
        #pragma unroll
        for (int j = 0; j < 16; ++j) {
            int e = tid + j * 512;
            cp_async16(sb + e * 16, src + e);
        }
        asm volatile("cp.async.commit_group;");
        asm volatile("cp.async.wait_group 0;");
    }
    __syncthreads();

    const float INF = __int_as_float(0x7f800000);

    for (;;) {
        int gid = 0;
        if (lane == 0) gid = atomicAdd(&g_work, 1);
        gid = __shfl_sync(0xffffffffu, gid, 0);
        if (gid >= NGROUPS) break;

        const int base = gid * 32;

        // A fragments (bf16), 2 m-tiles = 32 rows
        uint32_t Ah[2][4][4];
        #pragma unroll
        for (int m = 0; m < 2; ++m) {
            const float* xa = X + (size_t)(base + m * 16 + g) * DDIM;
            const float* xb = xa + 8 * DDIM;
            #pragma unroll
            for (int ks = 0; ks < 4; ++ks) {
                int ci = ks * 16 + 2 * t;
                Ah[m][ks][0] = packbf(xa[ci],     xa[ci + 1]);
                Ah[m][ks][1] = packbf(xb[ci],     xb[ci + 1]);
                Ah[m][ks][2] = packbf(xa[ci + 8], xa[ci + 9]);
                Ah[m][ks][3] = packbf(xb[ci + 8], xb[ci + 9]);
            }
        }

        // sorted top-3 of packed pair-minima per row-var
        uint32_t v[4][3];
        #pragma unroll
        for (int rv = 0; rv < 4; ++rv)
            v[rv][0] = v[rv][1] = v[rv][2] = 0xFFFFFFFFu;

        #pragma unroll 2
        for (int tt = 0; tt < 16; ++tt) {
            #pragma unroll
            for (int nb = 0; nb < 8; ++nb) {
                float c0[4] = {0.f, 0.f, 0.f, 0.f};
                float c1[4] = {0.f, 0.f, 0.f, 0.f};
                #pragma unroll
                for (int kp = 0; kp < 2; ++kp) {
                    uint4 b = *reinterpret_cast<const uint4*>(
                        &s_cb[(tt * 16 + nb * 2 + kp) * 128 + lane * 4]);
                    mma16(c0, Ah[0][2 * kp],     b.x, b.y);
                    mma16(c0, Ah[0][2 * kp + 1], b.z, b.w);
                    mma16(c1, Ah[1][2 * kp],     b.x, b.y);
                    mma16(c1, Ah[1][2 * kp + 1], b.z, b.w);
                }
                const uint32_t colb = tt * 64 + nb * 8 + 2 * t;
                float2 l2p = *reinterpret_cast<const float2*>(&s_l2[colb]);

                float q0 = fminf(fmaf(-2.f, c0[0], l2p.x), fmaf(-2.f, c0[1], l2p.y));
                float q1 = fminf(fmaf(-2.f, c0[2], l2p.x), fmaf(-2.f, c0[3], l2p.y));
                float q2 = fminf(fmaf(-2.f, c1[0], l2p.x), fmaf(-2.f, c1[1], l2p.y));
                float q3 = fminf(fmaf(-2.f, c1[2], l2p.x), fmaf(-2.f, c1[3], l2p.y));
                top3((__float_as_uint(q0) & 0xFFFFFC00u) | colb, v[0]);
                top3((__float_as_uint(q1) & 0xFFFFFC00u) | colb, v[1]);
                top3((__float_as_uint(q2) & 0xFFFFFC00u) | colb, v[2]);
                top3((__float_as_uint(q3) & 0xFFFFFC00u) | colb, v[3]);
            }
        }

        // quad-reduce min, window threshold, exact rescore of candidate pairs
        int bi[4];
        #pragma unroll
        for (int rv = 0; rv < 4; ++rv) {
            uint32_t m = v[rv][0];
            m = min(m, __shfl_xor_sync(0xffffffffu, m, 1));
            m = min(m, __shfl_xor_sync(0xffffffffu, m, 2));
            const float thr = __uint_as_float(m & 0xFFFFFC00u) + WINDOW;

            const int row = base + rv * 8 + g;
            float bd = INF;
            int   bk = 0x7fffffff;
            #pragma unroll
            for (int sl = 0; sl < 3; ++sl) {
                uint32_t p = v[rv][sl];
                if (__uint_as_float(p & 0xFFFFFC00u) <= thr) {
                    int kb = (int)(p & 0x3FFu);
                    exact_pair(X, CB, s_l2, row, kb, bd, bk);
                }
            }
            #pragma unroll
            for (int off = 1; off < 4; off <<= 1) {
                float od = __shfl_xor_sync(0xffffffffu, bd, off);
                int   ok = __shfl_xor_sync(0xffffffffu, bk, off);
                if (od < bd || (od == bd && ok < bk)) { bd = od; bk = ok; }
            }
            bi[rv] = bk;
        }

        if (t == 0) {
            #pragma unroll
            for (int rv = 0; rv < 4; ++rv) {
                g_idx[base + rv * 8 + g] = bi[rv];
                atomicAdd(&g_counts[bi[rv]], 1.0f);
            }
        }

        // scatter input sums: float4 vector atomics, 2 rows per iteration
        const float4* X4 = reinterpret_cast<const float4*>(X);
        #pragma unroll
        for (int rr = 0; rr < 32; rr += 2) {
            int r   = rr + (lane >> 4);
            int src = ((rr & 7) + (lane >> 4)) * 4;
            int idx = __shfl_sync(0xffffffffu, bi[rr >> 3], src);
            float4 vv = X4[(size_t)(base + r) * 16 + (lane & 15)];
            atomicAdd(reinterpret_cast<float4*>(g_isum + idx * DDIM) + (lane & 15), vv);
        }
    }
}

// ---------------------------------------------------------------------------
// Launch 4: fused EMA via smem transpose tile (all accesses coalesced).
// 32 blocks x 512 threads; block handles 32 k-values x 64 dims.
// tile pitch 65 -> conflict-free in both phases.
// ---------------------------------------------------------------------------
__global__ __launch_bounds__(512) void k_ema(
        const float* __restrict__ ema_cs,
        const float* __restrict__ ema_eis,
        float* __restrict__ out)
{
    __shared__ float tile[32 * 65];
    const int tid = threadIdx.x;
    const int kb  = blockIdx.x * 32;

    // load phase: g_isum rows k in [kb, kb+32), d-fast -> coalesced
    #pragma unroll
    for (int j = 0; j < 4; ++j) {
        int e = tid + j * 512;          // 0..2047
        int kl = e >> 6, d = e & 63;
        tile[kl * 65 + d] = g_isum[(size_t)(kb + kl) * DDIM + d];
    }
    __syncthreads();

    // compute phase: k-fast across lanes -> ema_eis/out accesses coalesced
    const int kl = tid & 31;
    const int k  = kb + kl;
    float ne = DECAY * ema_cs[k] + ONEMD * g_counts[k];
    if ((tid >> 5) == 0) out[OFF_ECS + k] = ne;

    const float n = DECAY * g_cs_sum + ONEMD * (float)N_ROWS;
    const float norm = (ne + EPS) / (n + (float)KCB * EPS);
    const float invcs = 1.0f / (norm * n);

    #pragma unroll
    for (int j = 0; j < 4; ++j) {
        int d = (tid >> 5) + j * 16;
        float eis = DECAY * ema_eis[d * KCB + k] + ONEMD * tile[kl * 65 + d];
        out[OFF_EIS + d * KCB + k] = eis;
        float nc = eis * invcs;
        out[OFF_NCB + d * KCB + k] = nc;
        tile[kl * 65 + d] = nc;         // stash for coalesced ncbT writeback
    }
    __syncthreads();

    // writeback phase: g_ncbT [k][d], d-fast -> coalesced
    #pragma unroll
    for (int j = 0; j < 4; ++j) {
        int e = tid + j * 512;
        int kl2 = e >> 6, d = e & 63;
        g_ncbT[(size_t)(kb + kl2) * DDIM + d] = tile[kl2 * 65 + d];
    }
}

// ---------------------------------------------------------------------------
// Launch 5: gather + straight-through + loss (float4, 4-way MLP)
// ---------------------------------------------------------------------------
__global__ __launch_bounds__(256) void k_gather_loss(
        const float* __restrict__ X, float* __restrict__ out)
{
    const int H = (N_ROWS * DDIM / 4) / 4;   // 524288
    const int eb = blockIdx.x * blockDim.x + threadIdx.x;
    const float4* X4 = reinterpret_cast<const float4*>(X);
    const float4* Q4 = reinterpret_cast<const float4*>(g_ncbT);
    float4* O4 = reinterpret_cast<float4*>(out + OFF_Q);

    int   ei[4];
    int   ii[4];
    float4 xv[4], qv[4];
    #pragma unroll
    for (int j = 0; j < 4; ++j) {
        ei[j] = eb + j * H;
        ii[j] = g_idx[ei[j] >> 4];
        xv[j] = X4[ei[j]];
    }
    #pragma unroll
    for (int j = 0; j < 4; ++j)
        qv[j] = Q4[(ii[j] << 4) | (ei[j] & 15)];

    float acc = 0.0f;
    #pragma unroll
    for (int j = 0; j < 4; ++j) {
        float dx = qv[j].x - xv[j].x, dy = qv[j].y - xv[j].y;
        float dz = qv[j].z - xv[j].z, dw = qv[j].w - xv[j].w;
        float4 o;
        o.x = xv[j].x + dx; o.y = xv[j].y + dy;
        o.z = xv[j].z + dz; o.w = xv[j].w + dw;
        O4[ei[j]] = o;
        acc = fmaf(dx, dx, acc); acc = fmaf(dy, dy, acc);
        acc = fmaf(dz, dz, acc); acc = fmaf(dw, dw, acc);
    }

    #pragma unroll
    for (int o2 = 16; o2 > 0; o2 >>= 1)
        acc += __shfl_down_sync(0xffffffffu, acc, o2);
    __shared__ float warpsum[8];
    int lane = threadIdx.x & 31, wid = threadIdx.x >> 5;
    if (lane == 0) warpsum[wid] = acc;
    __syncthreads();
    if (wid == 0) {
        float vv = (lane < 8) ? warpsum[lane] : 0.0f;
        #pragma unroll
        for (int o2 = 4; o2 > 0; o2 >>= 1)
            vv += __shfl_down_sync(0xffffffffu, vv, o2);
        if (lane == 0) atomicAdd(g_loss, vv);
    }
}

// Launch 6: finalize loss
__global__ void k_loss_finalize(float* __restrict__ out) {
    out[OFF_LOSS] = g_loss[0] * (1.0f / (float)(N_ROWS * DDIM));
}

// ---------------------------------------------------------------------------
extern "C" void kernel_launch(void* const* d_in, const int* in_sizes, int n_in,
                              void* d_out, int out_size) {
    const float* X       = (const float*)d_in[0];
    const float* CB      = (const float*)d_in[1];
    const float* EMA_CS  = (const float*)d_in[2];
    const float* EMA_EIS = (const float*)d_in[3];
    float* out = (float*)d_out;

    static const size_t dyn_smem = KCB * 4 + KCB * DDIM * 2;   // 4KB + 128KB
    cudaFuncSetAttribute(k_argmin_scatter,
                         cudaFuncAttributeMaxDynamicSharedMemorySize,
                         (int)dyn_smem);

    k_init_image<<<128, 256>>>(CB);                          // 0
    k_l2cb<<<16, 256>>>(CB, EMA_CS);                         // 1
    k_zero_small<<<1, 1024>>>();                             // 2
    k_argmin_scatter<<<GRID_A, BLOCK_A, dyn_smem>>>(X, CB);  // 3 (ncu)
    k_ema<<<32, 512>>>(EMA_CS, EMA_EIS, out);                // 4
    k_gather_loss<<<2048, 256>>>(X, out);                    // 5
    k_loss_finalize<<<1, 1>>>(out);                          // 6
}